// round 10
// baseline (speedup 1.0000x reference)
#include <cuda_runtime.h>

#define BB 64
#define SS 512
#define HH 768
#define TTAG 17
#define TPOS 45
#define MM (BB*SS)
#define MAXT 45

// ---- scratch (no allocations allowed) ----
__device__ float g_tag[MM*TTAG];
__device__ float g_pos[MM*TPOS];
__device__ float g_Etag[MM*TTAG];   // exp(e_j - e_0)
__device__ float g_Epos[MM*TPOS];
__device__ float g_diff[2*BB];
__device__ int   g_cnt;             // zero-init; reset by finalizing block

// ---- packed f32x2 helpers ----
__device__ __forceinline__ void fma2(unsigned long long& d,
                                     unsigned long long a, unsigned long long b) {
    asm("fma.rn.f32x2 %0, %1, %2, %3;" : "=l"(d) : "l"(a), "l"(b), "l"(d));
}
__device__ __forceinline__ unsigned long long add2(unsigned long long a, unsigned long long b) {
    unsigned long long d;
    asm("add.rn.f32x2 %0, %1, %2;" : "=l"(d) : "l"(a), "l"(b));
    return d;
}
__device__ __forceinline__ unsigned long long pack2(float lo, float hi) {
    unsigned long long d;
    asm("mov.b64 %0, {%1, %2};" : "=l"(d)
        : "r"(__float_as_uint(lo)), "r"(__float_as_uint(hi)));
    return d;
}
__device__ __forceinline__ void unpack2(unsigned long long v, float& lo, float& hi) {
    unsigned a, b;
    asm("mov.b64 {%0, %1}, %2;" : "=r"(a), "=r"(b) : "l"(v));
    lo = __uint_as_float(a); hi = __uint_as_float(b);
}

// ============================================================
// GEMM + fused E precompute (E = exp(e_j - e_0) per head)
// ============================================================
__global__ __launch_bounds__(256, 2) void gemm_kernel(
    const float* __restrict__ hidden,
    const float* __restrict__ Wt, const float* __restrict__ bt,
    const float* __restrict__ Wp, const float* __restrict__ bp)
{
    __shared__ float Hs[128*36];
    __shared__ float Ws[32*64];
    __shared__ float e0t[128], e0p[128];
    const int tid = threadIdx.x;
    const int ty = tid >> 4, tx = tid & 15;
    const int tok0 = blockIdx.x * 128;

    float acc[8][4];
#pragma unroll
    for (int i = 0; i < 8; i++)
#pragma unroll
        for (int j = 0; j < 4; j++) acc[i][j] = 0.f;

    float4 hreg[4];
    float  wreg[8];
    {
#pragma unroll
        for (int i = 0; i < 4; i++) {
            int idx = tid + i*256;
            int r = idx >> 3, c4 = idx & 7;
            hreg[i] = *reinterpret_cast<const float4*>(
                hidden + (size_t)(tok0 + r)*HH + c4*4);
        }
#pragma unroll
        for (int i = 0; i < 8; i++) {
            int idx = tid + i*256;
            int kk = idx >> 6, c = idx & 63;
            float v = 0.f;
            if (c < TTAG)    v = Wt[kk*TTAG + c];
            else if (c < 62) v = Wp[kk*TPOS + (c - TTAG)];
            wreg[i] = v;
        }
    }
    for (int ch = 0; ch < HH/32; ch++) {
#pragma unroll
        for (int i = 0; i < 4; i++) {
            int idx = tid + i*256;
            int r = idx >> 3, c4 = idx & 7;
            *reinterpret_cast<float4*>(&Hs[r*36 + c4*4]) = hreg[i];
        }
#pragma unroll
        for (int i = 0; i < 8; i++) Ws[tid + i*256] = wreg[i];
        __syncthreads();
        if (ch + 1 < HH/32) {
            const int k0 = (ch+1)*32;
#pragma unroll
            for (int i = 0; i < 4; i++) {
                int idx = tid + i*256;
                int r = idx >> 3, c4 = idx & 7;
                hreg[i] = *reinterpret_cast<const float4*>(
                    hidden + (size_t)(tok0 + r)*HH + k0 + c4*4);
            }
#pragma unroll
            for (int i = 0; i < 8; i++) {
                int idx = tid + i*256;
                int kk = idx >> 6, c = idx & 63;
                float v = 0.f;
                if (c < TTAG)    v = Wt[(k0+kk)*TTAG + c];
                else if (c < 62) v = Wp[(k0+kk)*TPOS + (c - TTAG)];
                wreg[i] = v;
            }
        }
#pragma unroll
        for (int kk = 0; kk < 32; kk++) {
            float4 bv = *reinterpret_cast<float4*>(&Ws[kk*64 + tx*4]);
#pragma unroll
            for (int i = 0; i < 8; i++) {
                float a = Hs[(ty*8+i)*36 + kk];
                acc[i][0] = fmaf(a, bv.x, acc[i][0]);
                acc[i][1] = fmaf(a, bv.y, acc[i][1]);
                acc[i][2] = fmaf(a, bv.z, acc[i][2]);
                acc[i][3] = fmaf(a, bv.w, acc[i][3]);
            }
        }
        __syncthreads();
    }
    // publish per-row e0 for both heads (tag col0 = c0; pos col0 = c17 -> tx=4,j=1)
#pragma unroll
    for (int i = 0; i < 8; i++) {
        if (tx == 0) e0t[ty*8+i] = acc[i][0] + bt[0];
        if (tx == 4) e0p[ty*8+i] = acc[i][1] + bp[0];
    }
    __syncthreads();
#pragma unroll
    for (int i = 0; i < 8; i++) {
        int rl = ty*8 + i;
        int r = tok0 + rl;
#pragma unroll
        for (int j = 0; j < 4; j++) {
            int c = tx*4 + j;
            if (c < TTAG) {
                float v = acc[i][j] + bt[c];
                g_tag [(size_t)r*TTAG + c] = v;
                g_Etag[(size_t)r*TTAG + c] = __expf(v - e0t[rl]);
            } else if (c < 62) {
                int cp = c - TTAG;
                float v = acc[i][j] + bp[cp];
                g_pos [(size_t)r*TPOS + cp] = v;
                g_Epos[(size_t)r*TPOS + cp] = __expf(v - e0p[rl]);
            }
        }
    }
}

// ============================================================
// CRF: one block per (head,batch). 160 threads:
//   warp 0:  self-contained forward (in-warp lag-2 rescale, no bar)
//   warps 1-3: Viterbi (2 lanes/col), bar.sync 2,96
//   warp 4:  numerator (one shot, no loop)
// ============================================================
struct __align__(16) CrfSmem {
    float a2[2][96];            // duplicated pairs (a_i,a_i)
    float sv[2][48];
    unsigned mword[16];
    float num_sh, den_sh;
    unsigned char path[SS];
    unsigned char hist[(SS-1)*MAXT];
    unsigned char comp[255*MAXT];   // 2-step compositions
};

template<int T>
__device__ __forceinline__ void crf_chain(
    CrfSmem& s,
    const float* __restrict__ stg, const float* __restrict__ trg,
    const float* __restrict__ eng,
    const int* __restrict__ tgt, const int* __restrict__ mask,
    const float* __restrict__ eb, const float* __restrict__ Eb, int b,
    float* __restrict__ pred)
{
    const int tid = threadIdx.x;
    const int w = tid >> 5, lane = tid & 31;
    constexpr int SHC = (T + 1) / 2;
    constexpr int BASE_B = (T/2) & ~3;
    constexpr int CA = T - BASE_B;
    constexpr int BIG = 1 << 20;

    // ---- init ----
    if (tid < 16) {
        unsigned bits = 0;
#pragma unroll
        for (int k = 0; k < 32; k++)
            bits |= (mask[b*SS + tid*32 + k] != 0 ? 1u : 0u) << k;
        s.mword[tid] = bits;
    }
    if (w >= 1 && w <= 3) {
        int vl = tid - 32, col = vl >> 1;
        if (col < T && !(vl & 1)) s.sv[0][col] = stg[col] + eb[col];
    }
    __syncthreads();

    if (w == 0) {
        // ================= forward warp (no barriers) =================
        const bool act = lane < SHC;
        const int j0 = act ? lane : 0;
        const bool j1ok = act && (lane + SHC < T);
        const int j1 = j1ok ? lane + SHC : j0;
        unsigned long long tc2[T];
#pragma unroll
        for (int i = 0; i < T; i++)
            tc2[i] = pack2(__expf(trg[i*T + j0]), __expf(trg[i*T + j1]));
        const float ref0 = stg[0] + eb[0];
        float acur0 = act  ? __expf(stg[j0] + eb[j0] - ref0) : 0.f;
        float acur1 = j1ok ? __expf(stg[j1] + eb[j1] - ref0) : 0.f;
        if (act) {
            *(unsigned long long*)&s.a2[0][2*j0] = pack2(acur0, acur0);
            if (j1ok) *(unsigned long long*)&s.a2[0][2*j1] = pack2(acur1, acur1);
        }
        __syncwarp();

        // emission/E prefetch queues (distance 2)
        float E0q1 = act  ? Eb[T + j0]   : 0.f;
        float E1q1 = j1ok ? Eb[T + j1]   : 0.f;
        float E0q2 = act  ? Eb[2*T + j0] : 0.f;
        float E1q2 = j1ok ? Eb[2*T + j1] : 0.f;
        float e0q1 = 0.f, e0q2 = 0.f, L = 0.f;
        if (lane == 0) { L = ref0; e0q1 = eb[T]; e0q2 = eb[2*T]; }

        // rescale pipeline: iv0 applied now, iv1 applied next step
        float vs = act ? acur0 + acur1 : 0.f;
#pragma unroll
        for (int o = 16; o > 0; o >>= 1) vs += __shfl_xor_sync(0xffffffffu, vs, o);
        float iv0 = 1.f;
        float iv1 = 1.f / vs;

        for (int t = 1; t < SS; t++) {
            const int pb = (t-1) & 1, cb = t & 1;
            const unsigned mt = (s.mword[t >> 5] >> (t & 31)) & 1u;
            float E0 = E0q1, E1 = E1q1;
            E0q1 = E0q2; E1q1 = E1q2;
            if (t + 2 < SS) {
                E0q2 = act  ? Eb[(size_t)(t+2)*T + j0] : 0.f;
                E1q2 = j1ok ? Eb[(size_t)(t+2)*T + j1] : 0.f;
            }
            unsigned long long d[4] = {0ull, 0ull, 0ull, 0ull};
            const float* ap = s.a2[pb];
#pragma unroll
            for (int k = 0; k < T/2; k++) {
                ulonglong2 q = *(const ulonglong2*)(ap + 4*k);
                fma2(d[(2*k) & 3],   q.x, tc2[2*k]);
                fma2(d[(2*k+1) & 3], q.y, tc2[2*k+1]);
            }
            if (T & 1) {
                unsigned long long qa = *(const unsigned long long*)(ap + 2*(T-1));
                fma2(d[(T-1) & 3], qa, tc2[T-1]);
            }
            unsigned long long dd = add2(add2(d[0], d[1]), add2(d[2], d[3]));
            float dot0, dot1; unpack2(dd, dot0, dot1);
            float v0 = (mt ? dot0 * E0 : acur0) * iv0;
            float v1 = (mt ? dot1 * E1 : acur1) * iv0;
            acur0 = v0; acur1 = v1;
            if (act) {
                *(unsigned long long*)&s.a2[cb][2*j0] = pack2(v0, v0);
                if (j1ok) *(unsigned long long*)&s.a2[cb][2*j1] = pack2(v1, v1);
            }
            __syncwarp();
            if (lane == 0) {
                float e0t_ = e0q1; e0q1 = e0q2;
                if (t + 2 < SS) e0q2 = eb[(size_t)(t+2)*T];
                if (mt) L += e0t_;
                L -= __logf(iv0);          // exact compensation of applied factor
            }
            float nvs = act ? v0 + v1 : 0.f;
#pragma unroll
            for (int o = 16; o > 0; o >>= 1) nvs += __shfl_xor_sync(0xffffffffu, nvs, o);
            iv0 = iv1;
            iv1 = 1.f / nvs;               // consumed 2 steps later
        }
        if (lane == 0) {
            float sm = 0.f;
#pragma unroll
            for (int i = 0; i < T; i++) sm += s.a2[1][2*i] * __expf(eng[i]);
            s.den_sh = L + __logf(sm);
        }
    } else if (w == 4) {
        // ================= numerator (one shot) =================
        float pacc = 0.f; int mxt = 0;
        for (int t = lane; t < SS; t += 32) {
            int tg = tgt[b*SS + t];
            if (t == 0) {
                pacc += stg[tg] + eb[tg];
            } else if (mask[b*SS + t] > 0) {
                int tgp = tgt[b*SS + t - 1];
                pacc += trg[tgp*T + tg] + eb[(size_t)t*T + tg];
                mxt = max(mxt, t);
            }
        }
#pragma unroll
        for (int o = 16; o > 0; o >>= 1) {
            pacc += __shfl_xor_sync(0xffffffffu, pacc, o);
            mxt = max(mxt, __shfl_xor_sync(0xffffffffu, mxt, o));
        }
        if (lane == 0) {
            int last = tgt[b*SS + mxt];
            s.num_sh = pacc + eng[last];
        }
    } else {
        // ================= viterbi warps (1-3) =================
        const int vl = tid - 32;
        const int col = vl >> 1;
        const bool act = col < T;
        const bool isA = !(vl & 1);
        const int jj = act ? col : 0;
        const int base = isA ? 0 : BASE_B;
        float tc[CA];
#pragma unroll
        for (int k = 0; k < CA; k++) tc[k] = trg[(base + k)*T + jj];
        float svprev = stg[jj] + eb[jj];
        float evq1 = eb[T + jj], evq2 = eb[2*T + jj];

        for (int t = 1; t < SS; t++) {
            const int pb = (t-1) & 1, cb = t & 1;
            float ev = evq1; evq1 = evq2;
            if (t + 2 < SS) evq2 = eb[(size_t)(t+2)*T + jj];

            float cand[CA];
            const float* sp = s.sv[pb] + base;
            constexpr int C4 = CA / 4;
#pragma unroll
            for (int k = 0; k < C4; k++) {
                float4 q = *(const float4*)(sp + 4*k);
                cand[4*k+0] = q.x + tc[4*k+0];
                cand[4*k+1] = q.y + tc[4*k+1];
                cand[4*k+2] = q.z + tc[4*k+2];
                cand[4*k+3] = q.w + tc[4*k+3];
            }
#pragma unroll
            for (int r = 4*C4; r < CA; r++) cand[r] = sp[r] + tc[r];

            // value max: 4-accumulator FMNMX trees (no predicates)
            float mx0 = -1e30f, mx1 = -1e30f, mx2 = -1e30f, mx3 = -1e30f;
#pragma unroll
            for (int k = 0; k < CA; k++) {
                if ((k & 3) == 0) mx0 = fmaxf(mx0, cand[k]);
                else if ((k & 3) == 1) mx1 = fmaxf(mx1, cand[k]);
                else if ((k & 3) == 2) mx2 = fmaxf(mx2, cand[k]);
                else mx3 = fmaxf(mx3, cand[k]);
            }
            float best = fmaxf(fmaxf(mx0, mx1), fmaxf(mx2, mx3));
            // index: min over equal-to-best (exact equality, independent ops)
            int ix0 = BIG, ix1 = BIG, ix2 = BIG, ix3 = BIG;
#pragma unroll
            for (int k = 0; k < CA; k++) {
                int cd = (cand[k] == best) ? (base + k) : BIG;
                if ((k & 3) == 0) ix0 = min(ix0, cd);
                else if ((k & 3) == 1) ix1 = min(ix1, cd);
                else if ((k & 3) == 2) ix2 = min(ix2, cd);
                else ix3 = min(ix3, cd);
            }
            int idx = min(min(ix0, ix1), min(ix2, ix3));
            // merge with partner lane (min index on value ties)
            float bo = __shfl_xor_sync(0xffffffffu, best, 1);
            int   io = __shfl_xor_sync(0xffffffffu, idx, 1);
            float bm = fmaxf(best, bo);
            int ia = (best == bm) ? idx : BIG;
            int ib = (bo == bm) ? io : BIG;
            int arg = min(ia, ib);

            if (isA && act) {
                unsigned mt = (s.mword[t >> 5] >> (t & 31)) & 1u;
                float svnew; int h;
                if (mt) { svnew = bm + ev; h = arg; }
                else    { svnew = svprev;  h = col; }
                s.sv[cb][col] = svnew;
                svprev = svnew;
                s.hist[(t-1)*T + col] = (unsigned char)h;
            }
            asm volatile("bar.sync 2, 96;" ::: "memory");
        }

        // ---- pointer-doubling backtrace ----
        // comp[k-1][j] = hist[(2k-2)][ hist[(2k-1)][j] ], k=1..255
        for (int idx = vl; idx < 255*T; idx += 96) {
            int k = idx / T + 1, j = idx - (k-1)*T;
            int a = s.hist[(2*k-1)*T + j];
            s.comp[(k-1)*T + j] = s.hist[(2*k-2)*T + a];
        }
        asm volatile("bar.sync 2, 96;" ::: "memory");
        if (tid == 32) {
            float bv = -1e30f; int cur = 0;
#pragma unroll
            for (int j = 0; j < T; j++) {
                float c = s.sv[1][j] + eng[j];
                if (c > bv) { bv = c; cur = j; }
            }
            s.path[SS-1] = (unsigned char)cur;
            cur = s.hist[(SS-2)*T + cur];         // M_511
            s.path[SS-2] = (unsigned char)cur;
            for (int k = 255; k >= 1; k--) {      // even positions 508..0
                cur = s.comp[(k-1)*T + cur];
                s.path[2*k - 2] = (unsigned char)cur;
            }
        }
        asm volatile("bar.sync 2, 96;" ::: "memory");
        // odd positions 1..509: path[t] = hist[t][path[t+1]]
        for (int t = 1 + 2*vl; t <= SS - 3; t += 192)
            s.path[t] = s.hist[t*T + s.path[t+1]];
        asm volatile("bar.sync 2, 96;" ::: "memory");
        if (w == 1)
            for (int i = lane; i < SS; i += 32) pred[i] = (float)s.path[i];
    }
}

__global__ __launch_bounds__(160) void crf_kernel(
    const float* __restrict__ st_t, const float* __restrict__ tr_t, const float* __restrict__ en_t,
    const float* __restrict__ st_p, const float* __restrict__ tr_p, const float* __restrict__ en_p,
    const int* __restrict__ tgt_t, const int* __restrict__ tgt_p,
    const int* __restrict__ mask,
    float* __restrict__ out, int out_size)
{
    __shared__ CrfSmem s;
    const int head = blockIdx.x >> 6;
    const int b    = blockIdx.x & 63;
    float* pred = out + (size_t)head*MM + (size_t)b*SS;
    if (head == 0)
        crf_chain<TTAG>(s, st_t, tr_t, en_t, tgt_t, mask,
                        g_tag  + (size_t)b*SS*TTAG,
                        g_Etag + (size_t)b*SS*TTAG, b, pred);
    else
        crf_chain<TPOS>(s, st_p, tr_p, en_p, tgt_p, mask,
                        g_pos  + (size_t)b*SS*TPOS,
                        g_Epos + (size_t)b*SS*TPOS, b, pred);
    __syncthreads();
    if (threadIdx.x == 0) {
        g_diff[head*BB + b] = s.num_sh - s.den_sh;
        __threadfence();
        int old = atomicAdd(&g_cnt, 1);
        if (old == 2*BB - 1) {
            __threadfence();
            float s0 = 0.f, s1 = 0.f;
            for (int i = 0; i < BB; i++) { s0 += g_diff[i]; s1 += g_diff[BB + i]; }
            if (out_size > 2*MM)     out[2*MM]     = -s0 / (float)BB;
            if (out_size > 2*MM + 1) out[2*MM + 1] = -s1 / (float)BB;
            g_cnt = 0;   // reset for next graph replay
        }
    }
}

extern "C" void kernel_launch(void* const* d_in, const int* in_sizes, int n_in,
                              void* d_out, int out_size)
{
    const float* hidden = (const float*)d_in[0];
    const int*   mask   = (const int*)d_in[1];
    const int*   tgt_t  = (const int*)d_in[2];
    const int*   tgt_p  = (const int*)d_in[3];
    const float* Wt     = (const float*)d_in[4];
    const float* bt     = (const float*)d_in[5];
    const float* Wp     = (const float*)d_in[6];
    const float* bp     = (const float*)d_in[7];
    const float* st_t   = (const float*)d_in[8];
    const float* tr_t   = (const float*)d_in[9];
    const float* en_t   = (const float*)d_in[10];
    const float* st_p   = (const float*)d_in[11];
    const float* tr_p   = (const float*)d_in[12];
    const float* en_p   = (const float*)d_in[13];
    float* out = (float*)d_out;

    gemm_kernel<<<MM/128, 256>>>(hidden, Wt, bt, Wp, bp);
    crf_kernel<<<2*BB, 160>>>(st_t, tr_t, en_t, st_p, tr_p, en_p,
                              tgt_t, tgt_p, mask, out, out_size);
}

// round 11
// speedup vs baseline: 1.2687x; 1.2687x over previous
#include <cuda_runtime.h>

#define BB 64
#define SS 512
#define HH 768
#define TTAG 17
#define TPOS 45
#define MM (BB*SS)
#define MAXT 45

// ---- scratch (no allocations allowed) ----
__device__ float g_tag[MM*TTAG];
__device__ float g_pos[MM*TPOS];
__device__ float g_Etag[MM*TTAG];   // exp(e_j - e_0)
__device__ float g_Epos[MM*TPOS];
__device__ float g_diff[2*BB];
__device__ int   g_cnt;             // zero-init; reset by finalizing block

// ---- packed f32x2 helpers ----
__device__ __forceinline__ void fma2(unsigned long long& d,
                                     unsigned long long a, unsigned long long b) {
    asm("fma.rn.f32x2 %0, %1, %2, %3;" : "=l"(d) : "l"(a), "l"(b), "l"(d));
}
__device__ __forceinline__ unsigned long long add2(unsigned long long a, unsigned long long b) {
    unsigned long long d;
    asm("add.rn.f32x2 %0, %1, %2;" : "=l"(d) : "l"(a), "l"(b));
    return d;
}
__device__ __forceinline__ unsigned long long pack2(float lo, float hi) {
    unsigned long long d;
    asm("mov.b64 %0, {%1, %2};" : "=l"(d)
        : "r"(__float_as_uint(lo)), "r"(__float_as_uint(hi)));
    return d;
}
__device__ __forceinline__ void unpack2(unsigned long long v, float& lo, float& hi) {
    unsigned a, b;
    asm("mov.b64 {%0, %1}, %2;" : "=r"(a), "=r"(b) : "l"(v));
    lo = __uint_as_float(a); hi = __uint_as_float(b);
}

// ============================================================
// GEMM + fused E precompute (validated in R10)
// ============================================================
__global__ __launch_bounds__(256, 2) void gemm_kernel(
    const float* __restrict__ hidden,
    const float* __restrict__ Wt, const float* __restrict__ bt,
    const float* __restrict__ Wp, const float* __restrict__ bp)
{
    __shared__ float Hs[128*36];
    __shared__ float Ws[32*64];
    __shared__ float e0t[128], e0p[128];
    const int tid = threadIdx.x;
    const int ty = tid >> 4, tx = tid & 15;
    const int tok0 = blockIdx.x * 128;

    float acc[8][4];
#pragma unroll
    for (int i = 0; i < 8; i++)
#pragma unroll
        for (int j = 0; j < 4; j++) acc[i][j] = 0.f;

    float4 hreg[4];
    float  wreg[8];
    {
#pragma unroll
        for (int i = 0; i < 4; i++) {
            int idx = tid + i*256;
            int r = idx >> 3, c4 = idx & 7;
            hreg[i] = *reinterpret_cast<const float4*>(
                hidden + (size_t)(tok0 + r)*HH + c4*4);
        }
#pragma unroll
        for (int i = 0; i < 8; i++) {
            int idx = tid + i*256;
            int kk = idx >> 6, c = idx & 63;
            float v = 0.f;
            if (c < TTAG)    v = Wt[kk*TTAG + c];
            else if (c < 62) v = Wp[kk*TPOS + (c - TTAG)];
            wreg[i] = v;
        }
    }
    for (int ch = 0; ch < HH/32; ch++) {
#pragma unroll
        for (int i = 0; i < 4; i++) {
            int idx = tid + i*256;
            int r = idx >> 3, c4 = idx & 7;
            *reinterpret_cast<float4*>(&Hs[r*36 + c4*4]) = hreg[i];
        }
#pragma unroll
        for (int i = 0; i < 8; i++) Ws[tid + i*256] = wreg[i];
        __syncthreads();
        if (ch + 1 < HH/32) {
            const int k0 = (ch+1)*32;
#pragma unroll
            for (int i = 0; i < 4; i++) {
                int idx = tid + i*256;
                int r = idx >> 3, c4 = idx & 7;
                hreg[i] = *reinterpret_cast<const float4*>(
                    hidden + (size_t)(tok0 + r)*HH + k0 + c4*4);
            }
#pragma unroll
            for (int i = 0; i < 8; i++) {
                int idx = tid + i*256;
                int kk = idx >> 6, c = idx & 63;
                float v = 0.f;
                if (c < TTAG)    v = Wt[(k0+kk)*TTAG + c];
                else if (c < 62) v = Wp[(k0+kk)*TPOS + (c - TTAG)];
                wreg[i] = v;
            }
        }
#pragma unroll
        for (int kk = 0; kk < 32; kk++) {
            float4 bv = *reinterpret_cast<float4*>(&Ws[kk*64 + tx*4]);
#pragma unroll
            for (int i = 0; i < 8; i++) {
                float a = Hs[(ty*8+i)*36 + kk];
                acc[i][0] = fmaf(a, bv.x, acc[i][0]);
                acc[i][1] = fmaf(a, bv.y, acc[i][1]);
                acc[i][2] = fmaf(a, bv.z, acc[i][2]);
                acc[i][3] = fmaf(a, bv.w, acc[i][3]);
            }
        }
        __syncthreads();
    }
#pragma unroll
    for (int i = 0; i < 8; i++) {
        if (tx == 0) e0t[ty*8+i] = acc[i][0] + bt[0];
        if (tx == 4) e0p[ty*8+i] = acc[i][1] + bp[0];
    }
    __syncthreads();
#pragma unroll
    for (int i = 0; i < 8; i++) {
        int rl = ty*8 + i;
        int r = tok0 + rl;
#pragma unroll
        for (int j = 0; j < 4; j++) {
            int c = tx*4 + j;
            if (c < TTAG) {
                float v = acc[i][j] + bt[c];
                g_tag [(size_t)r*TTAG + c] = v;
                g_Etag[(size_t)r*TTAG + c] = __expf(v - e0t[rl]);
            } else if (c < 62) {
                int cp = c - TTAG;
                float v = acc[i][j] + bp[cp];
                g_pos [(size_t)r*TPOS + cp] = v;
                g_Epos[(size_t)r*TPOS + cp] = __expf(v - e0p[rl]);
            }
        }
    }
}

// ============================================================
// CRF: one block per (head,batch). 160 threads:
//   warp 0:  forward recurrence (applies lag-2 normalizer)
//   warps 1-3: Viterbi (2 lanes/col), bar.sync 2,96
//   warp 4:  normalizer + L bookkeeping (writes lag slot), numerator after
//   warps 0,4 couple via bar.sync 1,64 (no intra-step dependency)
// ============================================================
struct __align__(16) CrfSmem {
    float a2[2][96];            // duplicated pairs (a_i,a_i)
    float sv[2][48];
    float invc[2];
    unsigned mword[16];
    float num_sh, den_sh;
    unsigned char path[SS];
    unsigned char hist[(SS-1)*MAXT];
    unsigned char comp[255*MAXT];
};

template<int T>
__device__ __forceinline__ void crf_chain(
    CrfSmem& s,
    const float* __restrict__ stg, const float* __restrict__ trg,
    const float* __restrict__ eng,
    const int* __restrict__ tgt, const int* __restrict__ mask,
    const float* __restrict__ eb, const float* __restrict__ Eb, int b,
    float* __restrict__ pred)
{
    const int tid = threadIdx.x;
    const int w = tid >> 5, lane = tid & 31;
    constexpr int SHC = (T + 1) / 2;
    constexpr int BASE_B = (T/2) & ~3;
    constexpr int CA = T - BASE_B;
    constexpr int BIG = 1 << 20;

    // ---- init ----
    if (tid < 16) {
        unsigned bits = 0;
#pragma unroll
        for (int k = 0; k < 32; k++)
            bits |= (mask[b*SS + tid*32 + k] != 0 ? 1u : 0u) << k;
        s.mword[tid] = bits;
    }
    if (tid == 0) { s.invc[0] = 1.f; s.invc[1] = 1.f; }
    if (w >= 1 && w <= 3) {
        int vl = tid - 32, col = vl >> 1;
        if (col < T && !(vl & 1)) s.sv[0][col] = stg[col] + eb[col];
    }
    __syncthreads();

    if (w == 0) {
        // ================= forward warp =================
        const bool act = lane < SHC;
        const int j0 = act ? lane : 0;
        const bool j1ok = act && (lane + SHC < T);
        const int j1 = j1ok ? lane + SHC : j0;
        unsigned long long tc2[T];
#pragma unroll
        for (int i = 0; i < T; i++)
            tc2[i] = pack2(__expf(trg[i*T + j0]), __expf(trg[i*T + j1]));
        const float ref0 = stg[0] + eb[0];
        float acur0 = act  ? __expf(stg[j0] + eb[j0] - ref0) : 0.f;
        float acur1 = j1ok ? __expf(stg[j1] + eb[j1] - ref0) : 0.f;
        if (act) {
            *(unsigned long long*)&s.a2[0][2*j0] = pack2(acur0, acur0);
            if (j1ok) *(unsigned long long*)&s.a2[0][2*j1] = pack2(acur1, acur1);
        }
        // E prefetch queue (distance 2)
        float E0q1 = act  ? Eb[T + j0]   : 0.f;
        float E1q1 = j1ok ? Eb[T + j1]   : 0.f;
        float E0q2 = act  ? Eb[2*T + j0] : 0.f;
        float E1q2 = j1ok ? Eb[2*T + j1] : 0.f;
        asm volatile("bar.sync 1, 64;" ::: "memory");

        for (int t = 1; t < SS; t++) {
            const int pb = (t-1) & 1, cb = t & 1;
            const unsigned mt = (s.mword[t >> 5] >> (t & 31)) & 1u;
            const float iv = s.invc[cb];       // lag slot: written at step t-1
            float E0 = E0q1, E1 = E1q1;
            E0q1 = E0q2; E1q1 = E1q2;
            if (t + 2 < SS) {
                E0q2 = act  ? Eb[(size_t)(t+2)*T + j0] : 0.f;
                E1q2 = j1ok ? Eb[(size_t)(t+2)*T + j1] : 0.f;
            }
            unsigned long long d[4] = {0ull, 0ull, 0ull, 0ull};
            const float* ap = s.a2[pb];
#pragma unroll
            for (int k = 0; k < T/2; k++) {
                ulonglong2 q = *(const ulonglong2*)(ap + 4*k);
                fma2(d[(2*k) & 3],   q.x, tc2[2*k]);
                fma2(d[(2*k+1) & 3], q.y, tc2[2*k+1]);
            }
            if (T & 1) {
                unsigned long long qa = *(const unsigned long long*)(ap + 2*(T-1));
                fma2(d[(T-1) & 3], qa, tc2[T-1]);
            }
            unsigned long long dd = add2(add2(d[0], d[1]), add2(d[2], d[3]));
            float dot0, dot1; unpack2(dd, dot0, dot1);
            float v0 = mt ? dot0 * E0 * iv : acur0;
            float v1 = mt ? dot1 * E1 * iv : acur1;
            acur0 = v0; acur1 = v1;
            if (act) {
                *(unsigned long long*)&s.a2[cb][2*j0] = pack2(v0, v0);
                if (j1ok) *(unsigned long long*)&s.a2[cb][2*j1] = pack2(v1, v1);
            }
            asm volatile("bar.sync 1, 64;" ::: "memory");
        }
    } else if (w == 4) {
        // ================= bookkeeping warp (lane 0) =================
        float priv[2] = {1.f, 1.f};
        float L = 0.f, e0q1 = 0.f, e0q2 = 0.f;
        if (lane == 0) { L = stg[0] + eb[0]; e0q1 = eb[T]; e0q2 = eb[2*T]; }
        asm volatile("bar.sync 1, 64;" ::: "memory");

        for (int t = 1; t < SS; t++) {
            const int pb = (t-1) & 1, cb = t & 1;
            if (lane == 0) {
                const unsigned mt = (s.mword[t >> 5] >> (t & 31)) & 1u;
                float e0t_ = e0q1; e0q1 = e0q2;
                if (t + 2 < SS) e0q2 = eb[(size_t)(t+2)*T];
                // compensate exactly the factor forward applied this step
                if (mt) L += e0t_ - __logf(priv[cb]);
                // compute next normalizer from state after step t-1 (vectorized)
                float s0 = 0.f, s1 = 0.f, s2 = 0.f, s3 = 0.f;
                const float* ap = s.a2[pb];
#pragma unroll
                for (int k = 0; k < T/2; k++) {
                    float4 q = *(const float4*)(ap + 4*k);
                    if (k & 1) { s0 += q.x; s1 += q.z; }
                    else       { s2 += q.x; s3 += q.z; }
                }
                if (T & 1) s0 += ap[2*(T-1)];
                float ninv = 1.f / ((s0 + s1) + (s2 + s3));
                priv[pb] = ninv;
                s.invc[pb] = ninv;     // forward applies at step t+1
            }
            asm volatile("bar.sync 1, 64;" ::: "memory");
        }
        if (lane == 0) {
            float sm = 0.f;
#pragma unroll
            for (int i = 0; i < T; i++) sm += s.a2[1][2*i] * __expf(eng[i]);
            s.den_sh = L + __logf(sm);
        }
        // numerator (parallel over t, one shot)
        float pacc = 0.f; int mxt = 0;
        for (int t = lane; t < SS; t += 32) {
            int tg = tgt[b*SS + t];
            if (t == 0) {
                pacc += stg[tg] + eb[tg];
            } else if (mask[b*SS + t] > 0) {
                int tgp = tgt[b*SS + t - 1];
                pacc += trg[tgp*T + tg] + eb[(size_t)t*T + tg];
                mxt = max(mxt, t);
            }
        }
#pragma unroll
        for (int o = 16; o > 0; o >>= 1) {
            pacc += __shfl_xor_sync(0xffffffffu, pacc, o);
            mxt = max(mxt, __shfl_xor_sync(0xffffffffu, mxt, o));
        }
        if (lane == 0) s.num_sh = pacc + eng[tgt[b*SS + mxt]];
    } else {
        // ================= viterbi warps (1-3) =================
        const int vl = tid - 32;
        const int col = vl >> 1;
        const bool act = col < T;
        const bool isA = !(vl & 1);
        const int jj = act ? col : 0;
        const int base = isA ? 0 : BASE_B;
        float tc[CA];
#pragma unroll
        for (int k = 0; k < CA; k++) tc[k] = trg[(base + k)*T + jj];
        float svprev = stg[jj] + eb[jj];
        float evq1 = eb[T + jj], evq2 = eb[2*T + jj];

        for (int t = 1; t < SS; t++) {
            const int pb = (t-1) & 1, cb = t & 1;
            float ev = evq1; evq1 = evq2;
            if (t + 2 < SS) evq2 = eb[(size_t)(t+2)*T + jj];

            float cand[CA];
            const float* sp = s.sv[pb] + base;
            constexpr int C4 = CA / 4;
#pragma unroll
            for (int k = 0; k < C4; k++) {
                float4 q = *(const float4*)(sp + 4*k);
                cand[4*k+0] = q.x + tc[4*k+0];
                cand[4*k+1] = q.y + tc[4*k+1];
                cand[4*k+2] = q.z + tc[4*k+2];
                cand[4*k+3] = q.w + tc[4*k+3];
            }
#pragma unroll
            for (int r = 4*C4; r < CA; r++) cand[r] = sp[r] + tc[r];

            float mx0 = -1e30f, mx1 = -1e30f, mx2 = -1e30f, mx3 = -1e30f;
#pragma unroll
            for (int k = 0; k < CA; k++) {
                if ((k & 3) == 0) mx0 = fmaxf(mx0, cand[k]);
                else if ((k & 3) == 1) mx1 = fmaxf(mx1, cand[k]);
                else if ((k & 3) == 2) mx2 = fmaxf(mx2, cand[k]);
                else mx3 = fmaxf(mx3, cand[k]);
            }
            float best = fmaxf(fmaxf(mx0, mx1), fmaxf(mx2, mx3));
            int ix0 = BIG, ix1 = BIG, ix2 = BIG, ix3 = BIG;
#pragma unroll
            for (int k = 0; k < CA; k++) {
                int cd = (cand[k] == best) ? (base + k) : BIG;
                if ((k & 3) == 0) ix0 = min(ix0, cd);
                else if ((k & 3) == 1) ix1 = min(ix1, cd);
                else if ((k & 3) == 2) ix2 = min(ix2, cd);
                else ix3 = min(ix3, cd);
            }
            int idx = min(min(ix0, ix1), min(ix2, ix3));
            float bo = __shfl_xor_sync(0xffffffffu, best, 1);
            int   io = __shfl_xor_sync(0xffffffffu, idx, 1);
            float bm = fmaxf(best, bo);
            int ia = (best == bm) ? idx : BIG;
            int ib = (bo == bm) ? io : BIG;
            int arg = min(ia, ib);

            if (isA && act) {
                unsigned mt = (s.mword[t >> 5] >> (t & 31)) & 1u;
                float svnew; int h;
                if (mt) { svnew = bm + ev; h = arg; }
                else    { svnew = svprev;  h = col; }
                s.sv[cb][col] = svnew;
                svprev = svnew;
                s.hist[(t-1)*T + col] = (unsigned char)h;
            }
            asm volatile("bar.sync 2, 96;" ::: "memory");
        }

        // ---- pointer-doubling backtrace ----
        for (int idx = vl; idx < 255*T; idx += 96) {
            int k = idx / T + 1, j = idx - (k-1)*T;
            int a = s.hist[(2*k-1)*T + j];
            s.comp[(k-1)*T + j] = s.hist[(2*k-2)*T + a];
        }
        asm volatile("bar.sync 2, 96;" ::: "memory");
        if (tid == 32) {
            float bv = -1e30f; int cur = 0;
#pragma unroll
            for (int j = 0; j < T; j++) {
                float c = s.sv[1][j] + eng[j];
                if (c > bv) { bv = c; cur = j; }
            }
            s.path[SS-1] = (unsigned char)cur;
            cur = s.hist[(SS-2)*T + cur];
            s.path[SS-2] = (unsigned char)cur;
            for (int k = 255; k >= 1; k--) {
                cur = s.comp[(k-1)*T + cur];
                s.path[2*k - 2] = (unsigned char)cur;
            }
        }
        asm volatile("bar.sync 2, 96;" ::: "memory");
        for (int t = 1 + 2*vl; t <= SS - 3; t += 192)
            s.path[t] = s.hist[t*T + s.path[t+1]];
        asm volatile("bar.sync 2, 96;" ::: "memory");
        if (w == 1)
            for (int i = lane; i < SS; i += 32) pred[i] = (float)s.path[i];
    }
}

__global__ __launch_bounds__(160) void crf_kernel(
    const float* __restrict__ st_t, const float* __restrict__ tr_t, const float* __restrict__ en_t,
    const float* __restrict__ st_p, const float* __restrict__ tr_p, const float* __restrict__ en_p,
    const int* __restrict__ tgt_t, const int* __restrict__ tgt_p,
    const int* __restrict__ mask,
    float* __restrict__ out, int out_size)
{
    __shared__ CrfSmem s;
    const int head = blockIdx.x >> 6;
    const int b    = blockIdx.x & 63;
    float* pred = out + (size_t)head*MM + (size_t)b*SS;
    if (head == 0)
        crf_chain<TTAG>(s, st_t, tr_t, en_t, tgt_t, mask,
                        g_tag  + (size_t)b*SS*TTAG,
                        g_Etag + (size_t)b*SS*TTAG, b, pred);
    else
        crf_chain<TPOS>(s, st_p, tr_p, en_p, tgt_p, mask,
                        g_pos  + (size_t)b*SS*TPOS,
                        g_Epos + (size_t)b*SS*TPOS, b, pred);
    __syncthreads();
    if (threadIdx.x == 0) {
        g_diff[head*BB + b] = s.num_sh - s.den_sh;
        __threadfence();
        int old = atomicAdd(&g_cnt, 1);
        if (old == 2*BB - 1) {
            __threadfence();
            float s0 = 0.f, s1 = 0.f;
            for (int i = 0; i < BB; i++) { s0 += g_diff[i]; s1 += g_diff[BB + i]; }
            if (out_size > 2*MM)     out[2*MM]     = -s0 / (float)BB;
            if (out_size > 2*MM + 1) out[2*MM + 1] = -s1 / (float)BB;
            g_cnt = 0;
        }
    }
}

extern "C" void kernel_launch(void* const* d_in, const int* in_sizes, int n_in,
                              void* d_out, int out_size)
{
    const float* hidden = (const float*)d_in[0];
    const int*   mask   = (const int*)d_in[1];
    const int*   tgt_t  = (const int*)d_in[2];
    const int*   tgt_p  = (const int*)d_in[3];
    const float* Wt     = (const float*)d_in[4];
    const float* bt     = (const float*)d_in[5];
    const float* Wp     = (const float*)d_in[6];
    const float* bp     = (const float*)d_in[7];
    const float* st_t   = (const float*)d_in[8];
    const float* tr_t   = (const float*)d_in[9];
    const float* en_t   = (const float*)d_in[10];
    const float* st_p   = (const float*)d_in[11];
    const float* tr_p   = (const float*)d_in[12];
    const float* en_p   = (const float*)d_in[13];
    float* out = (float*)d_out;

    gemm_kernel<<<MM/128, 256>>>(hidden, Wt, bt, Wp, bp);
    crf_kernel<<<2*BB, 160>>>(st_t, tr_t, en_t, st_p, tr_p, en_p,
                              tgt_t, tgt_p, mask, out, out_size);
}

// round 12
// speedup vs baseline: 1.3789x; 1.0868x over previous
#include <cuda_runtime.h>

#define BB 64
#define SS 512
#define HH 768
#define TTAG 17
#define TPOS 45
#define MM (BB*SS)
#define MAXT 45

// ---- scratch (no allocations allowed) ----
__device__ float g_tag[MM*TTAG];
__device__ float g_pos[MM*TPOS];
__device__ float g_Etag[MM*TTAG];   // exp(e_j - e_0)
__device__ float g_Epos[MM*TPOS];
__device__ float g_diff[2*BB];
__device__ int   g_cnt;             // zero-init; reset by finalizing block

// ---- packed f32x2 helpers ----
__device__ __forceinline__ void fma2(unsigned long long& d,
                                     unsigned long long a, unsigned long long b) {
    asm("fma.rn.f32x2 %0, %1, %2, %3;" : "=l"(d) : "l"(a), "l"(b), "l"(d));
}
__device__ __forceinline__ unsigned long long add2(unsigned long long a, unsigned long long b) {
    unsigned long long d;
    asm("add.rn.f32x2 %0, %1, %2;" : "=l"(d) : "l"(a), "l"(b));
    return d;
}
__device__ __forceinline__ unsigned long long pack2(float lo, float hi) {
    unsigned long long d;
    asm("mov.b64 %0, {%1, %2};" : "=l"(d)
        : "r"(__float_as_uint(lo)), "r"(__float_as_uint(hi)));
    return d;
}
__device__ __forceinline__ void unpack2(unsigned long long v, float& lo, float& hi) {
    unsigned a, b;
    asm("mov.b64 {%0, %1}, %2;" : "=r"(a), "=r"(b) : "l"(v));
    lo = __uint_as_float(a); hi = __uint_as_float(b);
}

// ============================================================
// GEMM + fused E precompute (validated R10/R11; ~103us)
// ============================================================
__global__ __launch_bounds__(256, 2) void gemm_kernel(
    const float* __restrict__ hidden,
    const float* __restrict__ Wt, const float* __restrict__ bt,
    const float* __restrict__ Wp, const float* __restrict__ bp)
{
    __shared__ float Hs[128*36];
    __shared__ float Ws[32*64];
    __shared__ float e0t[128], e0p[128];
    const int tid = threadIdx.x;
    const int ty = tid >> 4, tx = tid & 15;
    const int tok0 = blockIdx.x * 128;

    float acc[8][4];
#pragma unroll
    for (int i = 0; i < 8; i++)
#pragma unroll
        for (int j = 0; j < 4; j++) acc[i][j] = 0.f;

    float4 hreg[4];
    float  wreg[8];
    {
#pragma unroll
        for (int i = 0; i < 4; i++) {
            int idx = tid + i*256;
            int r = idx >> 3, c4 = idx & 7;
            hreg[i] = *reinterpret_cast<const float4*>(
                hidden + (size_t)(tok0 + r)*HH + c4*4);
        }
#pragma unroll
        for (int i = 0; i < 8; i++) {
            int idx = tid + i*256;
            int kk = idx >> 6, c = idx & 63;
            float v = 0.f;
            if (c < TTAG)    v = Wt[kk*TTAG + c];
            else if (c < 62) v = Wp[kk*TPOS + (c - TTAG)];
            wreg[i] = v;
        }
    }
    for (int ch = 0; ch < HH/32; ch++) {
#pragma unroll
        for (int i = 0; i < 4; i++) {
            int idx = tid + i*256;
            int r = idx >> 3, c4 = idx & 7;
            *reinterpret_cast<float4*>(&Hs[r*36 + c4*4]) = hreg[i];
        }
#pragma unroll
        for (int i = 0; i < 8; i++) Ws[tid + i*256] = wreg[i];
        __syncthreads();
        if (ch + 1 < HH/32) {
            const int k0 = (ch+1)*32;
#pragma unroll
            for (int i = 0; i < 4; i++) {
                int idx = tid + i*256;
                int r = idx >> 3, c4 = idx & 7;
                hreg[i] = *reinterpret_cast<const float4*>(
                    hidden + (size_t)(tok0 + r)*HH + k0 + c4*4);
            }
#pragma unroll
            for (int i = 0; i < 8; i++) {
                int idx = tid + i*256;
                int kk = idx >> 6, c = idx & 63;
                float v = 0.f;
                if (c < TTAG)    v = Wt[(k0+kk)*TTAG + c];
                else if (c < 62) v = Wp[(k0+kk)*TPOS + (c - TTAG)];
                wreg[i] = v;
            }
        }
#pragma unroll
        for (int kk = 0; kk < 32; kk++) {
            float4 bv = *reinterpret_cast<float4*>(&Ws[kk*64 + tx*4]);
#pragma unroll
            for (int i = 0; i < 8; i++) {
                float a = Hs[(ty*8+i)*36 + kk];
                acc[i][0] = fmaf(a, bv.x, acc[i][0]);
                acc[i][1] = fmaf(a, bv.y, acc[i][1]);
                acc[i][2] = fmaf(a, bv.z, acc[i][2]);
                acc[i][3] = fmaf(a, bv.w, acc[i][3]);
            }
        }
        __syncthreads();
    }
#pragma unroll
    for (int i = 0; i < 8; i++) {
        if (tx == 0) e0t[ty*8+i] = acc[i][0] + bt[0];
        if (tx == 4) e0p[ty*8+i] = acc[i][1] + bp[0];
    }
    __syncthreads();
#pragma unroll
    for (int i = 0; i < 8; i++) {
        int rl = ty*8 + i;
        int r = tok0 + rl;
#pragma unroll
        for (int j = 0; j < 4; j++) {
            int c = tx*4 + j;
            if (c < TTAG) {
                float v = acc[i][j] + bt[c];
                g_tag [(size_t)r*TTAG + c] = v;
                g_Etag[(size_t)r*TTAG + c] = __expf(v - e0t[rl]);
            } else if (c < 62) {
                int cp = c - TTAG;
                float v = acc[i][j] + bp[cp];
                g_pos [(size_t)r*TPOS + cp] = v;
                g_Epos[(size_t)r*TPOS + cp] = __expf(v - e0p[rl]);
            }
        }
    }
}

// ============================================================
// CRF: exact R9-config (fastest measured CRF ~190us)
//   warp 0: forward recurrence (FFMA2 packed, lag-1 invc)
//   warps 1-3: Viterbi (2 lanes/col, predicated chunks, shfl merge)
//   warp 4: normalizer bookkeeping + numerator epilogue
// named bars: id1 = {w0,w4} (64), id2 = {w1,w2,w3} (96)
// ============================================================
struct __align__(16) CrfSmem {
    float a2[2][96];       // duplicated pairs (a_i,a_i)
    float sv[2][48];
    float invc[2];
    unsigned mword[16];
    float num_sh, den_sh;
    unsigned char hist[(SS-1)*MAXT];
    unsigned char path[SS];
};

template<int T>
__device__ __forceinline__ void crf_chain(
    CrfSmem& s,
    const float* __restrict__ stg, const float* __restrict__ trg,
    const float* __restrict__ eng,
    const int* __restrict__ tgt, const int* __restrict__ mask,
    const float* __restrict__ eb, const float* __restrict__ Eb, int b)
{
    const int tid = threadIdx.x;
    const int w = tid >> 5, lane = tid & 31;
    constexpr int SHC = (T + 1) / 2;
    constexpr int BASE_B = (T/2) & ~3;
    constexpr int CA = T - BASE_B;

    // ---- init ----
    if (tid < 16) {
        unsigned bits = 0;
#pragma unroll
        for (int k = 0; k < 32; k++)
            bits |= (mask[b*SS + tid*32 + k] != 0 ? 1u : 0u) << k;
        s.mword[tid] = bits;
    }
    if (tid == 0) { s.invc[0] = 1.f; s.invc[1] = 1.f; }

    if (w == 0 && lane < SHC) {
        int j0 = lane, j1 = (lane + SHC < T) ? lane + SHC : lane;
        float r0 = stg[0] + eb[0];
        float a0 = __expf(stg[j0] + eb[j0] - r0);
        float a1 = __expf(stg[j1] + eb[j1] - r0);
        *(unsigned long long*)&s.a2[0][2*j0] = pack2(a0, a0);
        *(unsigned long long*)&s.a2[0][2*j1] = pack2(a1, a1);
    }
    if (w >= 1 && w <= 3) {
        int vl = tid - 32, col = vl >> 1;
        if (col < T && !(vl & 1)) s.sv[0][col] = stg[col] + eb[col];
    }
    __syncthreads();

    if (w == 0) {
        // ================= forward warp =================
        const bool act = lane < SHC;
        const int j0 = act ? lane : 0;
        const int j1 = (act && lane + SHC < T) ? lane + SHC : j0;
        unsigned long long tc2[T];
#pragma unroll
        for (int i = 0; i < T; i++)
            tc2[i] = pack2(__expf(trg[i*T + j0]), __expf(trg[i*T + j1]));
        float r0 = stg[0] + eb[0];
        float acur0 = __expf(stg[j0] + eb[j0] - r0);
        float acur1 = __expf(stg[j1] + eb[j1] - r0);
        float E0n = Eb[T + j0], E1n = Eb[T + j1];

        for (int t = 1; t < SS; t++) {
            const int pb = (t-1) & 1, cb = t & 1;
            float iv = s.invc[pb];
            unsigned mt = (s.mword[t >> 5] >> (t & 31)) & 1u;
            float E0 = E0n, E1 = E1n;
            if (t + 1 < SS) { E0n = Eb[(size_t)(t+1)*T + j0]; E1n = Eb[(size_t)(t+1)*T + j1]; }

            unsigned long long d[4] = {0ull, 0ull, 0ull, 0ull};
            const float* ap = s.a2[pb];
#pragma unroll
            for (int k = 0; k < T/2; k++) {
                ulonglong2 q = *(const ulonglong2*)(ap + 4*k);
                fma2(d[(2*k) & 3],   q.x, tc2[2*k]);
                fma2(d[(2*k+1) & 3], q.y, tc2[2*k+1]);
            }
            if (T & 1) {
                unsigned long long qa = *(const unsigned long long*)(ap + 2*(T-1));
                fma2(d[(T-1) & 3], qa, tc2[T-1]);
            }
            unsigned long long dd = add2(add2(d[0], d[1]), add2(d[2], d[3]));
            float dot0, dot1; unpack2(dd, dot0, dot1);
            float v0 = mt ? dot0 * iv * E0 : acur0;
            float v1 = mt ? dot1 * iv * E1 : acur1;
            acur0 = v0; acur1 = v1;
            if (act) {
                *(unsigned long long*)&s.a2[cb][2*j0] = pack2(v0, v0);
                *(unsigned long long*)&s.a2[cb][2*j1] = pack2(v1, v1);
            }
            asm volatile("bar.sync 1, 64;" ::: "memory");
        }
    } else if (w == 4) {
        // ================= bookkeeping warp =================
        float cpA = 1.f, cpB = 1.f, L = 0.f;
        float e0n = 0.f;
        if (lane == 0) { L = stg[0] + eb[0]; e0n = eb[T]; }
        for (int t = 1; t < SS; t++) {
            const int pb = (t-1) & 1, cb = t & 1;
            if (lane == 0) {
                unsigned mt = (s.mword[t >> 5] >> (t & 31)) & 1u;
                float e0t_ = e0n;
                if (t + 1 < SS) e0n = eb[(size_t)(t+1)*T];
                float sm0 = 0.f, sm1 = 0.f, sm2 = 0.f, sm3 = 0.f;
                const float* ap = s.a2[pb];
#pragma unroll
                for (int i = 0; i < T; i++) {
                    float v = ap[2*i];
                    if ((i & 3) == 0) sm0 += v;
                    else if ((i & 3) == 1) sm1 += v;
                    else if ((i & 3) == 2) sm2 += v;
                    else sm3 += v;
                }
                float sum = (sm0 + sm1) + (sm2 + sm3);
                float cp = pb ? cpB : cpA;
                if (mt) L += e0t_ - __logf(cp);
                float ninv = 1.f / sum;
                if (cb) cpB = ninv; else cpA = ninv;
                s.invc[cb] = ninv;
            }
            asm volatile("bar.sync 1, 64;" ::: "memory");
        }
        // numerator (parallel over t, epilogue)
        float pacc = 0.f; int mxt = 0;
        for (int t = lane; t < SS; t += 32) {
            int tg = tgt[b*SS + t];
            if (t == 0) {
                pacc += stg[tg] + eb[tg];
            } else if (mask[b*SS + t] > 0) {
                int tgp = tgt[b*SS + t - 1];
                pacc += trg[tgp*T + tg] + eb[(size_t)t*T + tg];
                mxt = max(mxt, t);
            }
        }
#pragma unroll
        for (int o = 16; o > 0; o >>= 1) {
            pacc += __shfl_xor_sync(0xffffffffu, pacc, o);
            mxt = max(mxt, __shfl_xor_sync(0xffffffffu, mxt, o));
        }
        if (lane == 0) {
            int last = tgt[b*SS + mxt];
            float num = pacc + eng[last];
            float sm = 0.f;
#pragma unroll
            for (int i = 0; i < T; i++) sm += s.a2[1][2*i] * __expf(eng[i]);
            float den = L + __logf(sm);
            s.num_sh = num;
            s.den_sh = den;
        }
    } else {
        // ================= viterbi warps (1-3) =================
        const int vl = tid - 32;
        const int col = vl >> 1;
        const bool act = col < T;
        const bool isA = !(vl & 1);
        const int jj = act ? col : 0;
        const int base = isA ? 0 : BASE_B;
        float tc[CA];
#pragma unroll
        for (int k = 0; k < CA; k++) tc[k] = trg[(base + k)*T + jj];
        float svprev = stg[jj] + eb[jj];
        float evcur = eb[T + jj];   // e[1][jj]

        for (int t = 1; t < SS; t++) {
            const int pb = (t-1) & 1, cb = t & 1;
            float evn = (t + 1 < SS) ? eb[(size_t)(t+1)*T + jj] : 0.f;
            float svv[CA];
            const float* sp = s.sv[pb] + base;
            constexpr int C4 = CA / 4;
#pragma unroll
            for (int k = 0; k < C4; k++) {
                float4 q = *(const float4*)(sp + 4*k);
                svv[4*k+0] = q.x; svv[4*k+1] = q.y;
                svv[4*k+2] = q.z; svv[4*k+3] = q.w;
            }
#pragma unroll
            for (int r = 4*C4; r < CA; r++) svv[r] = sp[r];
            // chunked first-argmax (contiguous chunks keep lowest-index ties)
            constexpr int NCH = (CA + 6) / 7;
            float bb[NCH]; int aa[NCH];
#pragma unroll
            for (int c = 0; c < NCH; c++) { bb[c] = -1e30f; aa[c] = 0; }
#pragma unroll
            for (int k = 0; k < CA; k++) {
                float cd = svv[k] + tc[k];
                int c = k / 7;
                if (cd > bb[c]) { bb[c] = cd; aa[c] = base + k; }
            }
            float best = bb[0]; int arg = aa[0];
#pragma unroll
            for (int c = 1; c < NCH; c++)
                if (bb[c] > best) { best = bb[c]; arg = aa[c]; }
            // exchange with partner lane (A holds prefix -> wins ties)
            float bo = __shfl_xor_sync(0xffffffffu, best, 1);
            int   ao = __shfl_xor_sync(0xffffffffu, arg, 1);
            if (isA && act) {
                if (bo > best) { best = bo; arg = ao; }
                unsigned mt = (s.mword[t >> 5] >> (t & 31)) & 1u;
                float e = evcur;
                float svnew; unsigned char h;
                if (mt) { svnew = best + e; h = (unsigned char)arg; }
                else    { svnew = svprev;   h = (unsigned char)col; }
                s.sv[cb][col] = svnew;
                svprev = svnew;
                s.hist[(t-1)*T + col] = h;
            }
            evcur = evn;
            asm volatile("bar.sync 2, 96;" ::: "memory");
        }
        // backtrace (warp 1, lane 0)
        if (tid == 32) {
            float bv = -1e30f; int cur = 0;
#pragma unroll
            for (int j = 0; j < T; j++) {
                float c = s.sv[1][j] + eng[j];
                if (c > bv) { bv = c; cur = j; }
            }
            s.path[SS-1] = (unsigned char)cur;
            for (int tt = SS-1; tt >= 1; tt--) {
                cur = s.hist[(tt-1)*T + cur];
                s.path[tt-1] = (unsigned char)cur;
            }
        }
    }
}

__global__ __launch_bounds__(160) void crf_kernel(
    const float* __restrict__ st_t, const float* __restrict__ tr_t, const float* __restrict__ en_t,
    const float* __restrict__ st_p, const float* __restrict__ tr_p, const float* __restrict__ en_p,
    const int* __restrict__ tgt_t, const int* __restrict__ tgt_p,
    const int* __restrict__ mask,
    float* __restrict__ out, int out_size)
{
    __shared__ CrfSmem s;
    const int head = blockIdx.x >> 6;
    const int b    = blockIdx.x & 63;
    float* pred = out + (size_t)head*MM + (size_t)b*SS;
    if (head == 0)
        crf_chain<TTAG>(s, st_t, tr_t, en_t, tgt_t, mask,
                        g_tag  + (size_t)b*SS*TTAG,
                        g_Etag + (size_t)b*SS*TTAG, b);
    else
        crf_chain<TPOS>(s, st_p, tr_p, en_p, tgt_p, mask,
                        g_pos  + (size_t)b*SS*TPOS,
                        g_Epos + (size_t)b*SS*TPOS, b);
    __syncthreads();
    // coalesced path write (warp 0 now free)
    if (threadIdx.x < 32)
        for (int i = threadIdx.x; i < SS; i += 32) pred[i] = (float)s.path[i];
    // fused finalize: last block sums all diffs
    if (threadIdx.x == 0) {
        g_diff[head*BB + b] = s.num_sh - s.den_sh;
        __threadfence();
        int old = atomicAdd(&g_cnt, 1);
        if (old == 2*BB - 1) {
            __threadfence();
            float s0 = 0.f, s1 = 0.f;
            for (int i = 0; i < BB; i++) { s0 += g_diff[i]; s1 += g_diff[BB + i]; }
            if (out_size > 2*MM)     out[2*MM]     = -s0 / (float)BB;
            if (out_size > 2*MM + 1) out[2*MM + 1] = -s1 / (float)BB;
            g_cnt = 0;   // reset for next graph replay
        }
    }
}

extern "C" void kernel_launch(void* const* d_in, const int* in_sizes, int n_in,
                              void* d_out, int out_size)
{
    const float* hidden = (const float*)d_in[0];
    const int*   mask   = (const int*)d_in[1];
    const int*   tgt_t  = (const int*)d_in[2];
    const int*   tgt_p  = (const int*)d_in[3];
    const float* Wt     = (const float*)d_in[4];
    const float* bt     = (const float*)d_in[5];
    const float* Wp     = (const float*)d_in[6];
    const float* bp     = (const float*)d_in[7];
    const float* st_t   = (const float*)d_in[8];
    const float* tr_t   = (const float*)d_in[9];
    const float* en_t   = (const float*)d_in[10];
    const float* st_p   = (const float*)d_in[11];
    const float* tr_p   = (const float*)d_in[12];
    const float* en_p   = (const float*)d_in[13];
    float* out = (float*)d_out;

    gemm_kernel<<<MM/128, 256>>>(hidden, Wt, bt, Wp, bp);
    crf_kernel<<<2*BB, 160>>>(st_t, tr_t, en_t, st_p, tr_p, en_p,
                              tgt_t, tgt_p, mask, out, out_size);
}